// round 10
// baseline (speedup 1.0000x reference)
#include <cuda_runtime.h>
#include <cuda_fp16.h>
#include <cstdint>

#define NF    16
#define NB    32768
#define NE    64
#define NO    64
#define NH    128
#define NHASH 200000
#define TILE_B 128

// fp16 tile strides (bytes)
#define S1B 144     // A1: K=64 halves + 8 pad
#define S2B 272     // H : K=128 halves + 8 pad

// dynamic smem: A1 and H are SEPARATE (no aliasing -> pair-local sync only)
#define OFF_A1HI 0              // [0, 18432)
#define OFF_A1LO 18432          // [18432, 36864)
#define OFF_HHI  36864          // [36864, 71680)
#define OFF_HLO  71680          // [71680, 106496)
#define SMEM_BYTES 106496

// Pre-split weight fragments in mma.m16n8k16 B-fragment lane layout.
// g_w1frag[((f*4 + ks)*16 + n8)*32 + lane] = {bhi0, bhi1, blo0, blo1}
__device__ __align__(16) uint4 g_w1frag[NF * 4 * 16 * 32];   // 512 KB
__device__ __align__(16) uint4 g_w2frag[NF * 8 * 8 * 32];    // 512 KB
__device__ int g_idx_is64;

__device__ __forceinline__ uint32_t smem_u32(const void* p) {
    uint32_t a;
    asm("{ .reg .u64 t; cvta.to.shared.u64 t, %1; cvt.u32.u64 %0, t; }" : "=r"(a) : "l"(p));
    return a;
}

__device__ __forceinline__ void ldsm_x4(uint32_t* r, uint32_t addr) {
    asm volatile("ldmatrix.sync.aligned.m8n8.x4.shared.b16 {%0,%1,%2,%3}, [%4];"
                 : "=r"(r[0]), "=r"(r[1]), "=r"(r[2]), "=r"(r[3]) : "r"(addr));
}

__device__ __forceinline__ void mma16816(float* d, const uint32_t* a, uint32_t b0, uint32_t b1) {
    asm volatile(
        "mma.sync.aligned.m16n8k16.row.col.f32.f16.f16.f32 "
        "{%0,%1,%2,%3}, {%4,%5,%6,%7}, {%8,%9}, {%0,%1,%2,%3};"
        : "+f"(d[0]), "+f"(d[1]), "+f"(d[2]), "+f"(d[3])
        : "r"(a[0]), "r"(a[1]), "r"(a[2]), "r"(a[3]), "r"(b0), "r"(b1));
}

__device__ __forceinline__ void split_h(float x, __half& hi, __half& lo) {
    hi = __float2half_rn(x);
    lo = __float2half_rn(x - __half2float(hi));
}

__device__ __forceinline__ uint32_t pack2(__half a, __half b) {
    __half2 p = __halves2half2(a, b);
    return *reinterpret_cast<uint32_t*>(&p);
}

// pair-scoped barrier: 64 threads (warps w and w+4), ids 1..4
#define PAIR_BAR(p) asm volatile("bar.sync %0, 64;" :: "r"((p) + 1) : "memory")

// ---------------- prep: idx dtype detect + weight fragment build ----------------
__global__ void prep_kernel(const float* __restrict__ W1,
                            const float* __restrict__ W2,
                            const int*   __restrict__ raw) {
    int g = blockIdx.x * blockDim.x + threadIdx.x;
    if (g == 0) {
        int any = 0;
#pragma unroll
        for (int i = 0; i < 64; i++) any |= raw[2 * i + 1];
        g_idx_is64 = (any == 0) ? 1 : 0;
    }
    if (g < NF * 4 * 16 * 32) {
        const int l  = g & 31;
        const int n8 = (g >> 5) & 15;
        const int ks = (g >> 9) & 3;
        const int f  = g >> 11;
        const int n  = n8 * 8 + (l >> 2);
        const int k0 = ks * 16 + (l & 3) * 2;
        const float* Wf = W1 + (size_t)f * NE * NH;
        float v00 = Wf[(k0 + 0) * NH + n];
        float v01 = Wf[(k0 + 1) * NH + n];
        float v10 = Wf[(k0 + 8) * NH + n];
        float v11 = Wf[(k0 + 9) * NH + n];
        __half h00, l00, h01, l01, h10, l10, h11, l11;
        split_h(v00, h00, l00); split_h(v01, h01, l01);
        split_h(v10, h10, l10); split_h(v11, h11, l11);
        uint4 r;
        r.x = pack2(h00, h01); r.y = pack2(h10, h11);
        r.z = pack2(l00, l01); r.w = pack2(l10, l11);
        g_w1frag[g] = r;
    } else {
        g -= NF * 4 * 16 * 32;
        const int l  = g & 31;
        const int n8 = (g >> 5) & 7;
        const int ks = (g >> 8) & 7;
        const int f  = g >> 11;
        const int n  = n8 * 8 + (l >> 2);
        const int k0 = ks * 16 + (l & 3) * 2;
        const float* Wf = W2 + (size_t)f * NH * NO;
        float v00 = Wf[(k0 + 0) * NO + n];
        float v01 = Wf[(k0 + 1) * NO + n];
        float v10 = Wf[(k0 + 8) * NO + n];
        float v11 = Wf[(k0 + 9) * NO + n];
        __half h00, l00, h01, l01, h10, l10, h11, l11;
        split_h(v00, h00, l00); split_h(v01, h01, l01);
        split_h(v10, h10, l10); split_h(v11, h11, l11);
        uint4 r;
        r.x = pack2(h00, h01); r.y = pack2(h10, h11);
        r.z = pack2(l00, l01); r.w = pack2(l10, l11);
        g_w2frag[g] = r;
    }
}

// ---------------- main kernel ----------------
__global__ __launch_bounds__(256, 2) void sparse_hmma_kernel(
    const int*   __restrict__ inputs_raw,
    const float* __restrict__ tables,
    const float* __restrict__ b1,
    const float* __restrict__ b2,
    float*       __restrict__ out)
{
    extern __shared__ char smem[];

    const uint32_t smem_u = smem_u32(smem);
    const int tid  = threadIdx.x;
    const int wid  = tid >> 5;
    const int lane = tid & 31;
    const int f    = blockIdx.y;
    const int row0 = blockIdx.x * TILE_B;
    const int is64 = g_idx_is64;

    const int pair   = wid & 3;        // m-tile id, rows [32*pair, 32*pair+32)
    const int nhalf  = wid >> 2;       // n-half for GEMM1 / GEMM2
    const int mbase  = pair * 32;

    // ---- gather: pair-local. 64 threads of the pair load its 32 rows ----
    {
        const int t64 = nhalf * 32 + lane;          // 0..63 within pair
        const int m   = mbase + (t64 >> 1);
        const int hf  = t64 & 1;
        const int flat = (row0 + m) * NF + f;
        const int v = is64 ? inputs_raw[2 * flat] : inputs_raw[flat];
        const int hidx = (v + 1) % NHASH;
        const float4* src =
            (const float4*)(tables + ((size_t)f * NHASH + hidx) * NE + hf * 32);
#pragma unroll
        for (int i = 0; i < 4; i++) {
            float4 va = src[2 * i];
            float4 vb = src[2 * i + 1];
            const int k = hf * 32 + i * 8;
            float vv[8] = {va.x, va.y, va.z, va.w, vb.x, vb.y, vb.z, vb.w};
            __half hi[8], lo[8];
#pragma unroll
            for (int j = 0; j < 8; j++) split_h(vv[j], hi[j], lo[j]);
            uint4 rhi, rlo;
            rhi.x = pack2(hi[0], hi[1]); rhi.y = pack2(hi[2], hi[3]);
            rhi.z = pack2(hi[4], hi[5]); rhi.w = pack2(hi[6], hi[7]);
            rlo.x = pack2(lo[0], lo[1]); rlo.y = pack2(lo[2], lo[3]);
            rlo.z = pack2(lo[4], lo[5]); rlo.w = pack2(lo[6], lo[7]);
            *(uint4*)(smem + OFF_A1HI + m * S1B + k * 2) = rhi;
            *(uint4*)(smem + OFF_A1LO + m * S1B + k * 2) = rlo;
        }
    }
    PAIR_BAR(pair);

    // ---- GEMM1: D1[32m x 64n] per warp = emb @ W1^T, 3-pass fp16, B from global ----
    const int nb8_1 = nhalf * 8;
    const uint32_t a_lane1 = (uint32_t)((lane & 15) * S1B + (lane >> 4) * 16);
    const uint32_t abhi1 = smem_u + OFF_A1HI + mbase * S1B + a_lane1;
    const uint32_t ablo1 = smem_u + OFF_A1LO + mbase * S1B + a_lane1;

    float acc1[2][8][4];
#pragma unroll
    for (int i = 0; i < 2; i++)
#pragma unroll
        for (int j = 0; j < 8; j++)
#pragma unroll
            for (int q = 0; q < 4; q++) acc1[i][j][q] = 0.0f;

#pragma unroll
    for (int ks = 0; ks < 4; ks++) {
        uint32_t ah0[4], ah1[4], al0[4], al1[4];
        ldsm_x4(ah0, abhi1 + ks * 32);
        ldsm_x4(ah1, abhi1 + 16 * S1B + ks * 32);
        ldsm_x4(al0, ablo1 + ks * 32);
        ldsm_x4(al1, ablo1 + 16 * S1B + ks * 32);
        const uint4* wp = g_w1frag + ((f * 4 + ks) * 16 + nb8_1) * 32 + lane;
#pragma unroll
        for (int nt = 0; nt < 8; nt++) {
            uint4 b = wp[nt * 32];
            mma16816(acc1[0][nt], ah0, b.x, b.y);
            mma16816(acc1[1][nt], ah1, b.x, b.y);
            mma16816(acc1[0][nt], al0, b.x, b.y);
            mma16816(acc1[1][nt], al1, b.x, b.y);
            mma16816(acc1[0][nt], ah0, b.z, b.w);
            mma16816(acc1[1][nt], ah1, b.z, b.w);
        }
    }

    // ---- epilogue1: H = relu(D1 + b1), hi/lo fp16 -> smem (pair-local region) ----
    const int nbase1 = nb8_1 * 8;
    const float* b1f = b1 + f * NH;
#pragma unroll
    for (int mt = 0; mt < 2; mt++) {
#pragma unroll
        for (int nt = 0; nt < 8; nt++) {
            const int r0 = mbase + mt * 16 + (lane >> 2);
            const int c0 = nbase1 + nt * 8 + 2 * (lane & 3);
            const float bx = __ldg(b1f + c0);
            const float by = __ldg(b1f + c0 + 1);
            const float* a = acc1[mt][nt];
            float v00 = fmaxf(a[0] + bx, 0.0f);
            float v01 = fmaxf(a[1] + by, 0.0f);
            float v10 = fmaxf(a[2] + bx, 0.0f);
            float v11 = fmaxf(a[3] + by, 0.0f);
            __half h00, l00, h01, l01, h10, l10, h11, l11;
            split_h(v00, h00, l00); split_h(v01, h01, l01);
            split_h(v10, h10, l10); split_h(v11, h11, l11);
            *(uint32_t*)(smem + OFF_HHI + r0 * S2B + c0 * 2) = pack2(h00, h01);
            *(uint32_t*)(smem + OFF_HLO + r0 * S2B + c0 * 2) = pack2(l00, l01);
            *(uint32_t*)(smem + OFF_HHI + (r0 + 8) * S2B + c0 * 2) = pack2(h10, h11);
            *(uint32_t*)(smem + OFF_HLO + (r0 + 8) * S2B + c0 * 2) = pack2(l10, l11);
        }
    }
    PAIR_BAR(pair);

    // ---- GEMM2: D2[32m x 32n] per warp = H @ W2^T, 3-pass fp16, B from global ----
    const int nb8_2 = nhalf * 4;
    const uint32_t a_lane2 = (uint32_t)((lane & 15) * S2B + (lane >> 4) * 16);
    const uint32_t abhi2 = smem_u + OFF_HHI + mbase * S2B + a_lane2;
    const uint32_t ablo2 = smem_u + OFF_HLO + mbase * S2B + a_lane2;

    float acc2[2][4][4];
#pragma unroll
    for (int i = 0; i < 2; i++)
#pragma unroll
        for (int j = 0; j < 4; j++)
#pragma unroll
            for (int q = 0; q < 4; q++) acc2[i][j][q] = 0.0f;

#pragma unroll
    for (int ks = 0; ks < 8; ks++) {
        uint32_t ah0[4], ah1[4], al0[4], al1[4];
        ldsm_x4(ah0, abhi2 + ks * 32);
        ldsm_x4(ah1, abhi2 + 16 * S2B + ks * 32);
        ldsm_x4(al0, ablo2 + ks * 32);
        ldsm_x4(al1, ablo2 + 16 * S2B + ks * 32);
        const uint4* wp = g_w2frag + ((f * 8 + ks) * 8 + nb8_2) * 32 + lane;
#pragma unroll
        for (int nt = 0; nt < 4; nt++) {
            uint4 b = wp[nt * 32];
            mma16816(acc2[0][nt], ah0, b.x, b.y);
            mma16816(acc2[1][nt], ah1, b.x, b.y);
            mma16816(acc2[0][nt], al0, b.x, b.y);
            mma16816(acc2[1][nt], al1, b.x, b.y);
            mma16816(acc2[0][nt], ah0, b.z, b.w);
            mma16816(acc2[1][nt], ah1, b.z, b.w);
        }
    }

    // ---- epilogue2: out = D2 + b2 ----
    const int nbase2 = nb8_2 * 8;
    const float* b2f = b2 + f * NO;
#pragma unroll
    for (int mt = 0; mt < 2; mt++) {
#pragma unroll
        for (int nt = 0; nt < 4; nt++) {
            const int gm = row0 + mbase + mt * 16 + (lane >> 2);
            const int o  = nbase2 + nt * 8 + 2 * (lane & 3);
            const float bx = __ldg(b2f + o);
            const float by = __ldg(b2f + o + 1);
            const float* a = acc2[mt][nt];
            float2 r0, r1;
            r0.x = a[0] + bx;
            r0.y = a[1] + by;
            r1.x = a[2] + bx;
            r1.y = a[3] + by;
            *(float2*)(out + ((size_t)f * NB + gm) * NO + o) = r0;
            *(float2*)(out + ((size_t)f * NB + gm + 8) * NO + o) = r1;
        }
    }
}

extern "C" void kernel_launch(void* const* d_in, const int* in_sizes, int n_in,
                              void* d_out, int out_size) {
    const int*   inputs_raw = (const int*)d_in[0];
    const float* tables     = (const float*)d_in[1];
    const float* W1         = (const float*)d_in[2];
    const float* b1         = (const float*)d_in[3];
    const float* W2         = (const float*)d_in[4];
    const float* b2         = (const float*)d_in[5];
    float*       out        = (float*)d_out;

    cudaFuncSetAttribute(sparse_hmma_kernel,
                         cudaFuncAttributeMaxDynamicSharedMemorySize, SMEM_BYTES);

    prep_kernel<<<256, 256>>>(W1, W2, inputs_raw);

    dim3 grid(NB / TILE_B, NF);
    sparse_hmma_kernel<<<grid, 256, SMEM_BYTES>>>(inputs_raw, tables, b1, b2, out);
}

// round 12
// speedup vs baseline: 1.3962x; 1.3962x over previous
#include <cuda_runtime.h>
#include <cuda_fp16.h>
#include <cstdint>

#define NF    16
#define NB    32768
#define NE    64
#define NO    64
#define NH    128
#define NHASH 200000
#define TILE_B 128

// fp16 tile strides (bytes)
#define S1B 144     // A1: K=64 halves + 8 pad
#define S2B 272     // H : K=128 halves + 8 pad

// dynamic smem byte offsets (H aliases A1 region, as in the 166us kernel)
#define OFF_A1HI 0              // 18432 B
#define OFF_A1LO 18432          // end 36864
#define OFF_HHI  0              // 34816 B
#define OFF_HLO  34816          // end 69632
#define SMEM_BYTES 69632

// Pre-split weight fragments in mma.m16n8k16 B-fragment lane layout.
// g_w1frag[((f*4 + ks)*16 + n8)*32 + lane] = {bhi0, bhi1, blo0, blo1}
__device__ __align__(16) uint4 g_w1frag[NF * 4 * 16 * 32];   // 512 KB
__device__ __align__(16) uint4 g_w2frag[NF * 8 * 8 * 32];    // 512 KB
__device__ int g_idx_is64;

__device__ __forceinline__ uint32_t smem_u32(const void* p) {
    uint32_t a;
    asm("{ .reg .u64 t; cvta.to.shared.u64 t, %1; cvt.u32.u64 %0, t; }" : "=r"(a) : "l"(p));
    return a;
}

__device__ __forceinline__ void ldsm_x4(uint32_t* r, uint32_t addr) {
    asm volatile("ldmatrix.sync.aligned.m8n8.x4.shared.b16 {%0,%1,%2,%3}, [%4];"
                 : "=r"(r[0]), "=r"(r[1]), "=r"(r[2]), "=r"(r[3]) : "r"(addr));
}

__device__ __forceinline__ void mma16816(float* d, const uint32_t* a, uint32_t b0, uint32_t b1) {
    asm volatile(
        "mma.sync.aligned.m16n8k16.row.col.f32.f16.f16.f32 "
        "{%0,%1,%2,%3}, {%4,%5,%6,%7}, {%8,%9}, {%0,%1,%2,%3};"
        : "+f"(d[0]), "+f"(d[1]), "+f"(d[2]), "+f"(d[3])
        : "r"(a[0]), "r"(a[1]), "r"(a[2]), "r"(a[3]), "r"(b0), "r"(b1));
}

__device__ __forceinline__ void split_h(float x, __half& hi, __half& lo) {
    hi = __float2half_rn(x);
    lo = __float2half_rn(x - __half2float(hi));
}

__device__ __forceinline__ uint32_t pack2(__half a, __half b) {
    __half2 p = __halves2half2(a, b);
    return *reinterpret_cast<uint32_t*>(&p);
}

// ---------------- prep: idx dtype detect + weight fragment build ----------------
__global__ void prep_kernel(const float* __restrict__ W1,
                            const float* __restrict__ W2,
                            const int*   __restrict__ raw) {
    int g = blockIdx.x * blockDim.x + threadIdx.x;
    if (g == 0) {
        int any = 0;
#pragma unroll
        for (int i = 0; i < 64; i++) any |= raw[2 * i + 1];
        g_idx_is64 = (any == 0) ? 1 : 0;
    }
    if (g < NF * 4 * 16 * 32) {
        const int l  = g & 31;
        const int n8 = (g >> 5) & 15;
        const int ks = (g >> 9) & 3;
        const int f  = g >> 11;
        const int n  = n8 * 8 + (l >> 2);
        const int k0 = ks * 16 + (l & 3) * 2;
        const float* Wf = W1 + (size_t)f * NE * NH;
        float v00 = Wf[(k0 + 0) * NH + n];
        float v01 = Wf[(k0 + 1) * NH + n];
        float v10 = Wf[(k0 + 8) * NH + n];
        float v11 = Wf[(k0 + 9) * NH + n];
        __half h00, l00, h01, l01, h10, l10, h11, l11;
        split_h(v00, h00, l00); split_h(v01, h01, l01);
        split_h(v10, h10, l10); split_h(v11, h11, l11);
        uint4 r;
        r.x = pack2(h00, h01); r.y = pack2(h10, h11);
        r.z = pack2(l00, l01); r.w = pack2(l10, l11);
        g_w1frag[g] = r;
    } else {
        g -= NF * 4 * 16 * 32;
        const int l  = g & 31;
        const int n8 = (g >> 5) & 7;
        const int ks = (g >> 8) & 7;
        const int f  = g >> 11;
        const int n  = n8 * 8 + (l >> 2);
        const int k0 = ks * 16 + (l & 3) * 2;
        const float* Wf = W2 + (size_t)f * NH * NO;
        float v00 = Wf[(k0 + 0) * NO + n];
        float v01 = Wf[(k0 + 1) * NO + n];
        float v10 = Wf[(k0 + 8) * NO + n];
        float v11 = Wf[(k0 + 9) * NO + n];
        __half h00, l00, h01, l01, h10, l10, h11, l11;
        split_h(v00, h00, l00); split_h(v01, h01, l01);
        split_h(v10, h10, l10); split_h(v11, h11, l11);
        uint4 r;
        r.x = pack2(h00, h01); r.y = pack2(h10, h11);
        r.z = pack2(l00, l01); r.w = pack2(l10, l11);
        g_w2frag[g] = r;
    }
}

// ---------------- main kernel ----------------
__global__ __launch_bounds__(256, 2) void sparse_hmma_kernel(
    const int*   __restrict__ inputs_raw,
    const float* __restrict__ tables,
    const float* __restrict__ b1,
    const float* __restrict__ b2,
    float*       __restrict__ out)
{
    extern __shared__ char smem[];
    __shared__ float b1s[NH];
    __shared__ float b2s[NO];

    const uint32_t smem_u = smem_u32(smem);
    const int tid  = threadIdx.x;
    const int wid  = tid >> 5;
    const int lane = tid & 31;
    const int f    = blockIdx.y;
    const int row0 = blockIdx.x * TILE_B;
    const int is64 = g_idx_is64;

    if (tid < NH) b1s[tid] = b1[f * NH + tid];
    if (tid < NO) b2s[tid] = b2[f * NO + tid];

    // ---- gather A1 = emb tile [m=128][k=64] hi/lo, 16B STS ----
    {
        const int m  = tid >> 1;
        const int hf = tid & 1;
        const int flat = (row0 + m) * NF + f;
        const int v = is64 ? inputs_raw[2 * flat] : inputs_raw[flat];
        const int hidx = (v + 1) % NHASH;
        const float4* src =
            (const float4*)(tables + ((size_t)f * NHASH + hidx) * NE + hf * 32);
#pragma unroll
        for (int i = 0; i < 4; i++) {
            float4 va = src[2 * i];
            float4 vb = src[2 * i + 1];
            const int k = hf * 32 + i * 8;
            float vv[8] = {va.x, va.y, va.z, va.w, vb.x, vb.y, vb.z, vb.w};
            __half hi[8], lo[8];
#pragma unroll
            for (int j = 0; j < 8; j++) split_h(vv[j], hi[j], lo[j]);
            uint4 rhi, rlo;
            rhi.x = pack2(hi[0], hi[1]); rhi.y = pack2(hi[2], hi[3]);
            rhi.z = pack2(hi[4], hi[5]); rhi.w = pack2(hi[6], hi[7]);
            rlo.x = pack2(lo[0], lo[1]); rlo.y = pack2(lo[2], lo[3]);
            rlo.z = pack2(lo[4], lo[5]); rlo.w = pack2(lo[6], lo[7]);
            *(uint4*)(smem + OFF_A1HI + m * S1B + k * 2) = rhi;
            *(uint4*)(smem + OFF_A1LO + m * S1B + k * 2) = rlo;
        }
    }
    __syncthreads();

    // ---- GEMM1: D1[32m x 64n] per warp = emb @ W1^T, 3-pass fp16 ----
    const int mbase = (wid & 3) * 32;
    const int nhalf = wid >> 2;
    const int nb8_1 = nhalf * 8;
    const uint32_t a_lane1 = (uint32_t)((lane & 15) * S1B + (lane >> 4) * 16);
    const uint32_t abhi1 = smem_u + OFF_A1HI + mbase * S1B + a_lane1;
    const uint32_t ablo1 = smem_u + OFF_A1LO + mbase * S1B + a_lane1;

    float acc1[2][8][4];
#pragma unroll
    for (int i = 0; i < 2; i++)
#pragma unroll
        for (int j = 0; j < 8; j++)
#pragma unroll
            for (int q = 0; q < 4; q++) acc1[i][j][q] = 0.0f;

#pragma unroll
    for (int ks = 0; ks < 4; ks++) {
        uint32_t ah0[4], ah1[4], al0[4], al1[4];
        ldsm_x4(ah0, abhi1 + ks * 32);
        ldsm_x4(ah1, abhi1 + 16 * S1B + ks * 32);
        ldsm_x4(al0, ablo1 + ks * 32);
        ldsm_x4(al1, ablo1 + 16 * S1B + ks * 32);
        const uint4* wp = g_w1frag + ((f * 4 + ks) * 16 + nb8_1) * 32 + lane;
#pragma unroll
        for (int nt = 0; nt < 8; nt++) {
            uint4 b = wp[nt * 32];
            mma16816(acc1[0][nt], ah0, b.x, b.y);
            mma16816(acc1[1][nt], ah1, b.x, b.y);
            mma16816(acc1[0][nt], al0, b.x, b.y);
            mma16816(acc1[1][nt], al1, b.x, b.y);
            mma16816(acc1[0][nt], ah0, b.z, b.w);
            mma16816(acc1[1][nt], ah1, b.z, b.w);
        }
    }

    __syncthreads();   // A1 reads done before H overwrites the region

    // ---- epilogue1: H = relu(D1 + b1) -> smem (for partner) + registers (own) ----
    // C-frag(mt, nt) == GEMM2 A-frag(mt, ks=nbase1/16 + nt/2):
    //   a0=c01(nt even), a1=c23(nt even), a2=c01(nt odd), a3=c23(nt odd)
    const int nbase1 = nb8_1 * 8;
    uint32_t hh[2][16], hl[2][16];     // [mt][ksl*4 + j]
#pragma unroll
    for (int mt = 0; mt < 2; mt++) {
#pragma unroll
        for (int nt = 0; nt < 8; nt++) {
            const int r0 = mbase + mt * 16 + (lane >> 2);
            const int c0 = nbase1 + nt * 8 + 2 * (lane & 3);
            const float* a = acc1[mt][nt];
            float v00 = fmaxf(a[0] + b1s[c0], 0.0f);
            float v01 = fmaxf(a[1] + b1s[c0 + 1], 0.0f);
            float v10 = fmaxf(a[2] + b1s[c0], 0.0f);
            float v11 = fmaxf(a[3] + b1s[c0 + 1], 0.0f);
            __half h00, l00, h01, l01, h10, l10, h11, l11;
            split_h(v00, h00, l00); split_h(v01, h01, l01);
            split_h(v10, h10, l10); split_h(v11, h11, l11);
            const uint32_t pc01h = pack2(h00, h01), pc23h = pack2(h10, h11);
            const uint32_t pc01l = pack2(l00, l01), pc23l = pack2(l10, l11);
            const int pos = (nt >> 1) * 4 + (nt & 1) * 2;
            hh[mt][pos]     = pc01h;
            hh[mt][pos + 1] = pc23h;
            hl[mt][pos]     = pc01l;
            hl[mt][pos + 1] = pc23l;
            *(uint32_t*)(smem + OFF_HHI + r0 * S2B + c0 * 2) = pc01h;
            *(uint32_t*)(smem + OFF_HLO + r0 * S2B + c0 * 2) = pc01l;
            *(uint32_t*)(smem + OFF_HHI + (r0 + 8) * S2B + c0 * 2) = pc23h;
            *(uint32_t*)(smem + OFF_HLO + (r0 + 8) * S2B + c0 * 2) = pc23l;
        }
    }
    __syncthreads();

    // ---- GEMM2: D2[32m x 32n] per warp = H @ W2^T, 3-pass fp16 ----
    // Own k-slices ks in [4*nhalf, 4*nhalf+4): A-frags from registers.
    // Partner k-slices: ldmatrix from smem.
    const int nb8_2 = nhalf * 4;
    const uint32_t a_lane2 = (uint32_t)((lane & 15) * S2B + (lane >> 4) * 16);
    const uint32_t abhi2 = smem_u + OFF_HHI + mbase * S2B + a_lane2;
    const uint32_t ablo2 = smem_u + OFF_HLO + mbase * S2B + a_lane2;

    float acc2[2][4][4];
#pragma unroll
    for (int i = 0; i < 2; i++)
#pragma unroll
        for (int j = 0; j < 4; j++)
#pragma unroll
            for (int q = 0; q < 4; q++) acc2[i][j][q] = 0.0f;

    // partner half: ldmatrix path
    const int pks0 = (1 - nhalf) * 4;
#pragma unroll
    for (int ksl = 0; ksl < 4; ksl++) {
        const int ks = pks0 + ksl;
        uint32_t ah0[4], ah1[4], al0[4], al1[4];
        ldsm_x4(ah0, abhi2 + ks * 32);
        ldsm_x4(ah1, abhi2 + 16 * S2B + ks * 32);
        ldsm_x4(al0, ablo2 + ks * 32);
        ldsm_x4(al1, ablo2 + 16 * S2B + ks * 32);
        const uint4* wp = g_w2frag + ((f * 8 + ks) * 8 + nb8_2) * 32 + lane;
#pragma unroll
        for (int nt = 0; nt < 4; nt++) {
            uint4 b = wp[nt * 32];
            mma16816(acc2[0][nt], ah0, b.x, b.y);
            mma16816(acc2[1][nt], ah1, b.x, b.y);
            mma16816(acc2[0][nt], al0, b.x, b.y);
            mma16816(acc2[1][nt], al1, b.x, b.y);
            mma16816(acc2[0][nt], ah0, b.z, b.w);
            mma16816(acc2[1][nt], ah1, b.z, b.w);
        }
    }
    // own half: register path
    const int oks0 = nhalf * 4;
#pragma unroll
    for (int ksl = 0; ksl < 4; ksl++) {
        const int ks = oks0 + ksl;
        const uint32_t* ah0 = &hh[0][ksl * 4];
        const uint32_t* ah1 = &hh[1][ksl * 4];
        const uint32_t* al0 = &hl[0][ksl * 4];
        const uint32_t* al1 = &hl[1][ksl * 4];
        const uint4* wp = g_w2frag + ((f * 8 + ks) * 8 + nb8_2) * 32 + lane;
#pragma unroll
        for (int nt = 0; nt < 4; nt++) {
            uint4 b = wp[nt * 32];
            mma16816(acc2[0][nt], ah0, b.x, b.y);
            mma16816(acc2[1][nt], ah1, b.x, b.y);
            mma16816(acc2[0][nt], al0, b.x, b.y);
            mma16816(acc2[1][nt], al1, b.x, b.y);
            mma16816(acc2[0][nt], ah0, b.z, b.w);
            mma16816(acc2[1][nt], ah1, b.z, b.w);
        }
    }

    // ---- epilogue2: out = D2 + b2 ----
    const int nbase2 = nb8_2 * 8;
#pragma unroll
    for (int mt = 0; mt < 2; mt++) {
#pragma unroll
        for (int nt = 0; nt < 4; nt++) {
            const int gm = row0 + mbase + mt * 16 + (lane >> 2);
            const int o  = nbase2 + nt * 8 + 2 * (lane & 3);
            const float* a = acc2[mt][nt];
            float2 r0, r1;
            r0.x = a[0] + b2s[o];
            r0.y = a[1] + b2s[o + 1];
            r1.x = a[2] + b2s[o];
            r1.y = a[3] + b2s[o + 1];
            *(float2*)(out + ((size_t)f * NB + gm) * NO + o) = r0;
            *(float2*)(out + ((size_t)f * NB + gm + 8) * NO + o) = r1;
        }
    }
}

extern "C" void kernel_launch(void* const* d_in, const int* in_sizes, int n_in,
                              void* d_out, int out_size) {
    const int*   inputs_raw = (const int*)d_in[0];
    const float* tables     = (const float*)d_in[1];
    const float* W1         = (const float*)d_in[2];
    const float* b1         = (const float*)d_in[3];
    const float* W2         = (const float*)d_in[4];
    const float* b2         = (const float*)d_in[5];
    float*       out        = (float*)d_out;

    cudaFuncSetAttribute(sparse_hmma_kernel,
                         cudaFuncAttributeMaxDynamicSharedMemorySize, SMEM_BYTES);

    prep_kernel<<<256, 256>>>(W1, W2, inputs_raw);

    dim3 grid(NB / TILE_B, NF);
    sparse_hmma_kernel<<<grid, 256, SMEM_BYTES>>>(inputs_raw, tables, b1, b2, out);
}

// round 13
// speedup vs baseline: 1.6909x; 1.2111x over previous
#include <cuda_runtime.h>
#include <cuda_fp16.h>
#include <cstdint>

#define NF    16
#define NB    32768
#define NE    64
#define NO    64
#define NH    128
#define NHASH 200000
#define TILE_B 64

// fp16 tile strides (bytes)
#define S1B 144     // A1: K=64 halves + 8 pad
#define S2B 272     // H : K=128 halves + 8 pad

// dynamic smem byte offsets (H aliases A1 region)
#define OFF_A1HI 0              // 64 x 144 = 9216
#define OFF_A1LO 9216           // end 18432
#define OFF_HHI  0              // 64 x 272 = 17408
#define OFF_HLO  17408          // end 34816
#define SMEM_BYTES 34816

// Pre-split weight fragments in mma.m16n8k16 B-fragment lane layout.
// g_w1frag[((f*4 + ks)*16 + n8)*32 + lane] = {bhi0, bhi1, blo0, blo1}
__device__ __align__(16) uint4 g_w1frag[NF * 4 * 16 * 32];   // 512 KB
__device__ __align__(16) uint4 g_w2frag[NF * 8 * 8 * 32];    // 512 KB
__device__ int g_idx_is64;

__device__ __forceinline__ uint32_t smem_u32(const void* p) {
    uint32_t a;
    asm("{ .reg .u64 t; cvta.to.shared.u64 t, %1; cvt.u32.u64 %0, t; }" : "=r"(a) : "l"(p));
    return a;
}

__device__ __forceinline__ void ldsm_x4(uint32_t* r, uint32_t addr) {
    asm volatile("ldmatrix.sync.aligned.m8n8.x4.shared.b16 {%0,%1,%2,%3}, [%4];"
                 : "=r"(r[0]), "=r"(r[1]), "=r"(r[2]), "=r"(r[3]) : "r"(addr));
}

__device__ __forceinline__ void mma16816(float* d, const uint32_t* a, uint32_t b0, uint32_t b1) {
    asm volatile(
        "mma.sync.aligned.m16n8k16.row.col.f32.f16.f16.f32 "
        "{%0,%1,%2,%3}, {%4,%5,%6,%7}, {%8,%9}, {%0,%1,%2,%3};"
        : "+f"(d[0]), "+f"(d[1]), "+f"(d[2]), "+f"(d[3])
        : "r"(a[0]), "r"(a[1]), "r"(a[2]), "r"(a[3]), "r"(b0), "r"(b1));
}

__device__ __forceinline__ void split_h(float x, __half& hi, __half& lo) {
    hi = __float2half_rn(x);
    lo = __float2half_rn(x - __half2float(hi));
}

__device__ __forceinline__ uint32_t pack2(__half a, __half b) {
    __half2 p = __halves2half2(a, b);
    return *reinterpret_cast<uint32_t*>(&p);
}

// ---------------- prep: idx dtype detect + weight fragment build ----------------
__global__ void prep_kernel(const float* __restrict__ W1,
                            const float* __restrict__ W2,
                            const int*   __restrict__ raw) {
    int g = blockIdx.x * blockDim.x + threadIdx.x;
    if (g == 0) {
        int any = 0;
#pragma unroll
        for (int i = 0; i < 64; i++) any |= raw[2 * i + 1];
        g_idx_is64 = (any == 0) ? 1 : 0;
    }
    if (g < NF * 4 * 16 * 32) {
        const int l  = g & 31;
        const int n8 = (g >> 5) & 15;
        const int ks = (g >> 9) & 3;
        const int f  = g >> 11;
        const int n  = n8 * 8 + (l >> 2);
        const int k0 = ks * 16 + (l & 3) * 2;
        const float* Wf = W1 + (size_t)f * NE * NH;
        float v00 = Wf[(k0 + 0) * NH + n];
        float v01 = Wf[(k0 + 1) * NH + n];
        float v10 = Wf[(k0 + 8) * NH + n];
        float v11 = Wf[(k0 + 9) * NH + n];
        __half h00, l00, h01, l01, h10, l10, h11, l11;
        split_h(v00, h00, l00); split_h(v01, h01, l01);
        split_h(v10, h10, l10); split_h(v11, h11, l11);
        uint4 r;
        r.x = pack2(h00, h01); r.y = pack2(h10, h11);
        r.z = pack2(l00, l01); r.w = pack2(l10, l11);
        g_w1frag[g] = r;
    } else {
        g -= NF * 4 * 16 * 32;
        const int l  = g & 31;
        const int n8 = (g >> 5) & 7;
        const int ks = (g >> 8) & 7;
        const int f  = g >> 11;
        const int n  = n8 * 8 + (l >> 2);
        const int k0 = ks * 16 + (l & 3) * 2;
        const float* Wf = W2 + (size_t)f * NH * NO;
        float v00 = Wf[(k0 + 0) * NO + n];
        float v01 = Wf[(k0 + 1) * NO + n];
        float v10 = Wf[(k0 + 8) * NO + n];
        float v11 = Wf[(k0 + 9) * NO + n];
        __half h00, l00, h01, l01, h10, l10, h11, l11;
        split_h(v00, h00, l00); split_h(v01, h01, l01);
        split_h(v10, h10, l10); split_h(v11, h11, l11);
        uint4 r;
        r.x = pack2(h00, h01); r.y = pack2(h10, h11);
        r.z = pack2(l00, l01); r.w = pack2(l10, l11);
        g_w2frag[g] = r;
    }
}

// ---------------- main kernel (128 threads, 4 warps, 64-row tile) ----------------
__global__ __launch_bounds__(128, 4) void sparse_hmma_kernel(
    const int*   __restrict__ inputs_raw,
    const float* __restrict__ tables,
    const float* __restrict__ b1,
    const float* __restrict__ b2,
    float*       __restrict__ out)
{
    extern __shared__ char smem[];
    __shared__ float b1s[NH];
    __shared__ float b2s[NO];

    const uint32_t smem_u = smem_u32(smem);
    const int tid  = threadIdx.x;
    const int wid  = tid >> 5;
    const int lane = tid & 31;
    const int f    = blockIdx.y;
    const int row0 = blockIdx.x * TILE_B;
    const int is64 = g_idx_is64;

    if (tid < NH) b1s[tid] = b1[f * NH + tid];
    if (tid < NO) b2s[tid] = b2[f * NO + tid];

    // ---- gather A1 = emb tile [m=64][k=64] hi/lo, 16B STS ----
    {
        const int m  = tid >> 1;
        const int hf = tid & 1;
        const int flat = (row0 + m) * NF + f;
        const int v = is64 ? inputs_raw[2 * flat] : inputs_raw[flat];
        const int hidx = (v + 1) % NHASH;
        const float4* src =
            (const float4*)(tables + ((size_t)f * NHASH + hidx) * NE + hf * 32);
#pragma unroll
        for (int i = 0; i < 4; i++) {
            float4 va = src[2 * i];
            float4 vb = src[2 * i + 1];
            const int k = hf * 32 + i * 8;
            float vv[8] = {va.x, va.y, va.z, va.w, vb.x, vb.y, vb.z, vb.w};
            __half hi[8], lo[8];
#pragma unroll
            for (int j = 0; j < 8; j++) split_h(vv[j], hi[j], lo[j]);
            uint4 rhi, rlo;
            rhi.x = pack2(hi[0], hi[1]); rhi.y = pack2(hi[2], hi[3]);
            rhi.z = pack2(hi[4], hi[5]); rhi.w = pack2(hi[6], hi[7]);
            rlo.x = pack2(lo[0], lo[1]); rlo.y = pack2(lo[2], lo[3]);
            rlo.z = pack2(lo[4], lo[5]); rlo.w = pack2(lo[6], lo[7]);
            *(uint4*)(smem + OFF_A1HI + m * S1B + k * 2) = rhi;
            *(uint4*)(smem + OFF_A1LO + m * S1B + k * 2) = rlo;
        }
    }
    __syncthreads();

    // ---- GEMM1: D1[32m x 64n] per warp = emb @ W1^T, 3-pass fp16 ----
    const int mbase = (wid & 1) * 32;
    const int nb8_1 = (wid >> 1) * 8;      // n8 base (8 n-tiles per warp)
    const uint32_t a_lane1 = (uint32_t)((lane & 15) * S1B + (lane >> 4) * 16);
    const uint32_t abhi1 = smem_u + OFF_A1HI + mbase * S1B + a_lane1;
    const uint32_t ablo1 = smem_u + OFF_A1LO + mbase * S1B + a_lane1;

    float acc1[2][8][4];
#pragma unroll
    for (int i = 0; i < 2; i++)
#pragma unroll
        for (int j = 0; j < 8; j++)
#pragma unroll
            for (int q = 0; q < 4; q++) acc1[i][j][q] = 0.0f;

#pragma unroll
    for (int ks = 0; ks < 4; ks++) {
        uint32_t ah0[4], ah1[4], al0[4], al1[4];
        ldsm_x4(ah0, abhi1 + ks * 32);
        ldsm_x4(ah1, abhi1 + 16 * S1B + ks * 32);
        ldsm_x4(al0, ablo1 + ks * 32);
        ldsm_x4(al1, ablo1 + 16 * S1B + ks * 32);
        const uint4* wp = g_w1frag + ((f * 4 + ks) * 16 + nb8_1) * 32 + lane;
#pragma unroll
        for (int nt = 0; nt < 8; nt++) {
            uint4 b = wp[nt * 32];
            mma16816(acc1[0][nt], ah0, b.x, b.y);
            mma16816(acc1[1][nt], ah1, b.x, b.y);
            mma16816(acc1[0][nt], al0, b.x, b.y);
            mma16816(acc1[1][nt], al1, b.x, b.y);
            mma16816(acc1[0][nt], ah0, b.z, b.w);
            mma16816(acc1[1][nt], ah1, b.z, b.w);
        }
    }

    __syncthreads();   // A1 reads done before H overwrites the region

    // ---- epilogue1: H = relu(D1 + b1), hi/lo fp16 -> smem ----
    const int nbase1 = nb8_1 * 8;
#pragma unroll
    for (int mt = 0; mt < 2; mt++) {
#pragma unroll
        for (int nt = 0; nt < 8; nt++) {
            const int r0 = mbase + mt * 16 + (lane >> 2);
            const int c0 = nbase1 + nt * 8 + 2 * (lane & 3);
            const float* a = acc1[mt][nt];
            float v00 = fmaxf(a[0] + b1s[c0], 0.0f);
            float v01 = fmaxf(a[1] + b1s[c0 + 1], 0.0f);
            float v10 = fmaxf(a[2] + b1s[c0], 0.0f);
            float v11 = fmaxf(a[3] + b1s[c0 + 1], 0.0f);
            __half h00, l00, h01, l01, h10, l10, h11, l11;
            split_h(v00, h00, l00); split_h(v01, h01, l01);
            split_h(v10, h10, l10); split_h(v11, h11, l11);
            *(uint32_t*)(smem + OFF_HHI + r0 * S2B + c0 * 2) = pack2(h00, h01);
            *(uint32_t*)(smem + OFF_HLO + r0 * S2B + c0 * 2) = pack2(l00, l01);
            *(uint32_t*)(smem + OFF_HHI + (r0 + 8) * S2B + c0 * 2) = pack2(h10, h11);
            *(uint32_t*)(smem + OFF_HLO + (r0 + 8) * S2B + c0 * 2) = pack2(l10, l11);
        }
    }
    __syncthreads();

    // ---- GEMM2: D2[32m x 32n] per warp = H @ W2^T, 3-pass fp16 ----
    const int nb8_2 = (wid >> 1) * 4;      // n8 base (4 n-tiles per warp)
    const uint32_t a_lane2 = (uint32_t)((lane & 15) * S2B + (lane >> 4) * 16);
    const uint32_t abhi2 = smem_u + OFF_HHI + mbase * S2B + a_lane2;
    const uint32_t ablo2 = smem_u + OFF_HLO + mbase * S2B + a_lane2;

    float acc2[2][4][4];
#pragma unroll
    for (int i = 0; i < 2; i++)
#pragma unroll
        for (int j = 0; j < 4; j++)
#pragma unroll
            for (int q = 0; q < 4; q++) acc2[i][j][q] = 0.0f;

#pragma unroll
    for (int ks = 0; ks < 8; ks++) {
        uint32_t ah0[4], ah1[4], al0[4], al1[4];
        ldsm_x4(ah0, abhi2 + ks * 32);
        ldsm_x4(ah1, abhi2 + 16 * S2B + ks * 32);
        ldsm_x4(al0, ablo2 + ks * 32);
        ldsm_x4(al1, ablo2 + 16 * S2B + ks * 32);
        const uint4* wp = g_w2frag + ((f * 8 + ks) * 8 + nb8_2) * 32 + lane;
#pragma unroll
        for (int nt = 0; nt < 4; nt++) {
            uint4 b = wp[nt * 32];
            mma16816(acc2[0][nt], ah0, b.x, b.y);
            mma16816(acc2[1][nt], ah1, b.x, b.y);
            mma16816(acc2[0][nt], al0, b.x, b.y);
            mma16816(acc2[1][nt], al1, b.x, b.y);
            mma16816(acc2[0][nt], ah0, b.z, b.w);
            mma16816(acc2[1][nt], ah1, b.z, b.w);
        }
    }

    // ---- epilogue2: out = D2 + b2 ----
    const int nbase2 = nb8_2 * 8;
#pragma unroll
    for (int mt = 0; mt < 2; mt++) {
#pragma unroll
        for (int nt = 0; nt < 4; nt++) {
            const int gm = row0 + mbase + mt * 16 + (lane >> 2);
            const int o  = nbase2 + nt * 8 + 2 * (lane & 3);
            const float* a = acc2[mt][nt];
            float2 r0, r1;
            r0.x = a[0] + b2s[o];
            r0.y = a[1] + b2s[o + 1];
            r1.x = a[2] + b2s[o];
            r1.y = a[3] + b2s[o + 1];
            *(float2*)(out + ((size_t)f * NB + gm) * NO + o) = r0;
            *(float2*)(out + ((size_t)f * NB + gm + 8) * NO + o) = r1;
        }
    }
}

extern "C" void kernel_launch(void* const* d_in, const int* in_sizes, int n_in,
                              void* d_out, int out_size) {
    const int*   inputs_raw = (const int*)d_in[0];
    const float* tables     = (const float*)d_in[1];
    const float* W1         = (const float*)d_in[2];
    const float* b1         = (const float*)d_in[3];
    const float* W2         = (const float*)d_in[4];
    const float* b2         = (const float*)d_in[5];
    float*       out        = (float*)d_out;

    cudaFuncSetAttribute(sparse_hmma_kernel,
                         cudaFuncAttributeMaxDynamicSharedMemorySize, SMEM_BYTES);

    prep_kernel<<<256, 256>>>(W1, W2, inputs_raw);

    dim3 grid(NB / TILE_B, NF);
    sparse_hmma_kernel<<<grid, 128, SMEM_BYTES>>>(inputs_raw, tables, b1, b2, out);
}

// round 14
// speedup vs baseline: 2.0264x; 1.1984x over previous
#include <cuda_runtime.h>
#include <cuda_fp16.h>
#include <cstdint>

#define NF    16
#define NB    32768
#define NE    64
#define NO    64
#define NH    128
#define NHASH 200000
#define TILE_B 64

// fp16 tile strides (bytes)
#define S1B 144     // A1: K=64 halves + 8 pad
#define S2B 272     // H : K=128 halves + 8 pad

// dynamic smem byte offsets (H aliases A1; hi-only now)
#define OFF_A1HI 0              // 64 x 144 = 9216
#define OFF_HHI  0              // 64 x 272 = 17408
#define SMEM_BYTES 17408

// Pre-split weight fragments in mma.m16n8k16 B-fragment lane layout.
// g_w1frag[((f*4 + ks)*16 + n8)*32 + lane] = {bhi0, bhi1, blo0, blo1}
__device__ __align__(16) uint4 g_w1frag[NF * 4 * 16 * 32];   // 512 KB
__device__ __align__(16) uint4 g_w2frag[NF * 8 * 8 * 32];    // 512 KB
__device__ int g_idx_is64;

__device__ __forceinline__ uint32_t smem_u32(const void* p) {
    uint32_t a;
    asm("{ .reg .u64 t; cvta.to.shared.u64 t, %1; cvt.u32.u64 %0, t; }" : "=r"(a) : "l"(p));
    return a;
}

__device__ __forceinline__ void ldsm_x4(uint32_t* r, uint32_t addr) {
    asm volatile("ldmatrix.sync.aligned.m8n8.x4.shared.b16 {%0,%1,%2,%3}, [%4];"
                 : "=r"(r[0]), "=r"(r[1]), "=r"(r[2]), "=r"(r[3]) : "r"(addr));
}

__device__ __forceinline__ void mma16816(float* d, const uint32_t* a, uint32_t b0, uint32_t b1) {
    asm volatile(
        "mma.sync.aligned.m16n8k16.row.col.f32.f16.f16.f32 "
        "{%0,%1,%2,%3}, {%4,%5,%6,%7}, {%8,%9}, {%0,%1,%2,%3};"
        : "+f"(d[0]), "+f"(d[1]), "+f"(d[2]), "+f"(d[3])
        : "r"(a[0]), "r"(a[1]), "r"(a[2]), "r"(a[3]), "r"(b0), "r"(b1));
}

__device__ __forceinline__ void split_h(float x, __half& hi, __half& lo) {
    hi = __float2half_rn(x);
    lo = __float2half_rn(x - __half2float(hi));
}

__device__ __forceinline__ uint32_t pack2(__half a, __half b) {
    __half2 p = __halves2half2(a, b);
    return *reinterpret_cast<uint32_t*>(&p);
}

// ---------------- prep: idx dtype detect + weight fragment build ----------------
__global__ void prep_kernel(const float* __restrict__ W1,
                            const float* __restrict__ W2,
                            const int*   __restrict__ raw) {
    int g = blockIdx.x * blockDim.x + threadIdx.x;
    if (g == 0) {
        int any = 0;
#pragma unroll
        for (int i = 0; i < 64; i++) any |= raw[2 * i + 1];
        g_idx_is64 = (any == 0) ? 1 : 0;
    }
    if (g < NF * 4 * 16 * 32) {
        const int l  = g & 31;
        const int n8 = (g >> 5) & 15;
        const int ks = (g >> 9) & 3;
        const int f  = g >> 11;
        const int n  = n8 * 8 + (l >> 2);
        const int k0 = ks * 16 + (l & 3) * 2;
        const float* Wf = W1 + (size_t)f * NE * NH;
        float v00 = Wf[(k0 + 0) * NH + n];
        float v01 = Wf[(k0 + 1) * NH + n];
        float v10 = Wf[(k0 + 8) * NH + n];
        float v11 = Wf[(k0 + 9) * NH + n];
        __half h00, l00, h01, l01, h10, l10, h11, l11;
        split_h(v00, h00, l00); split_h(v01, h01, l01);
        split_h(v10, h10, l10); split_h(v11, h11, l11);
        uint4 r;
        r.x = pack2(h00, h01); r.y = pack2(h10, h11);
        r.z = pack2(l00, l01); r.w = pack2(l10, l11);
        g_w1frag[g] = r;
    } else {
        g -= NF * 4 * 16 * 32;
        const int l  = g & 31;
        const int n8 = (g >> 5) & 7;
        const int ks = (g >> 8) & 7;
        const int f  = g >> 11;
        const int n  = n8 * 8 + (l >> 2);
        const int k0 = ks * 16 + (l & 3) * 2;
        const float* Wf = W2 + (size_t)f * NH * NO;
        float v00 = Wf[(k0 + 0) * NO + n];
        float v01 = Wf[(k0 + 1) * NO + n];
        float v10 = Wf[(k0 + 8) * NO + n];
        float v11 = Wf[(k0 + 9) * NO + n];
        __half h00, l00, h01, l01, h10, l10, h11, l11;
        split_h(v00, h00, l00); split_h(v01, h01, l01);
        split_h(v10, h10, l10); split_h(v11, h11, l11);
        uint4 r;
        r.x = pack2(h00, h01); r.y = pack2(h10, h11);
        r.z = pack2(l00, l01); r.w = pack2(l10, l11);
        g_w2frag[g] = r;
    }
}

// ---------------- main kernel (128 threads, 4 warps, 64-row tile) ----------------
__global__ __launch_bounds__(128, 4) void sparse_hmma_kernel(
    const int*   __restrict__ inputs_raw,
    const float* __restrict__ tables,
    const float* __restrict__ b1,
    const float* __restrict__ b2,
    float*       __restrict__ out)
{
    extern __shared__ char smem[];
    __shared__ float b1s[NH];
    __shared__ float b2s[NO];

    const uint32_t smem_u = smem_u32(smem);
    const int tid  = threadIdx.x;
    const int wid  = tid >> 5;
    const int lane = tid & 31;
    const int f    = blockIdx.y;
    const int row0 = blockIdx.x * TILE_B;
    const int is64 = g_idx_is64;

    if (tid < NH) b1s[tid] = b1[f * NH + tid];
    if (tid < NO) b2s[tid] = b2[f * NO + tid];

    // ---- gather A1 = emb tile [m=64][k=64], fp16 hi only, 16B STS ----
    {
        const int m  = tid >> 1;
        const int hf = tid & 1;
        const int flat = (row0 + m) * NF + f;
        const int v = is64 ? inputs_raw[2 * flat] : inputs_raw[flat];
        const int hidx = (v + 1) % NHASH;
        const float4* src =
            (const float4*)(tables + ((size_t)f * NHASH + hidx) * NE + hf * 32);
#pragma unroll
        for (int i = 0; i < 4; i++) {
            float4 va = src[2 * i];
            float4 vb = src[2 * i + 1];
            const int k = hf * 32 + i * 8;
            uint4 rhi;
            rhi.x = pack2(__float2half_rn(va.x), __float2half_rn(va.y));
            rhi.y = pack2(__float2half_rn(va.z), __float2half_rn(va.w));
            rhi.z = pack2(__float2half_rn(vb.x), __float2half_rn(vb.y));
            rhi.w = pack2(__float2half_rn(vb.z), __float2half_rn(vb.w));
            *(uint4*)(smem + OFF_A1HI + m * S1B + k * 2) = rhi;
        }
    }
    __syncthreads();

    // ---- GEMM1: D1[32m x 64n] per warp = emb_hi @ (W1_hi + W1_lo)^T, 2-pass ----
    const int mbase = (wid & 1) * 32;
    const int nb8_1 = (wid >> 1) * 8;      // n8 base (8 n-tiles per warp)
    const uint32_t a_lane1 = (uint32_t)((lane & 15) * S1B + (lane >> 4) * 16);
    const uint32_t abhi1 = smem_u + OFF_A1HI + mbase * S1B + a_lane1;

    float acc1[2][8][4];
#pragma unroll
    for (int i = 0; i < 2; i++)
#pragma unroll
        for (int j = 0; j < 8; j++)
#pragma unroll
            for (int q = 0; q < 4; q++) acc1[i][j][q] = 0.0f;

#pragma unroll
    for (int ks = 0; ks < 4; ks++) {
        uint32_t ah0[4], ah1[4];
        ldsm_x4(ah0, abhi1 + ks * 32);
        ldsm_x4(ah1, abhi1 + 16 * S1B + ks * 32);
        const uint4* wp = g_w1frag + ((f * 4 + ks) * 16 + nb8_1) * 32 + lane;
#pragma unroll
        for (int nt = 0; nt < 8; nt++) {
            uint4 b = wp[nt * 32];
            mma16816(acc1[0][nt], ah0, b.x, b.y);
            mma16816(acc1[1][nt], ah1, b.x, b.y);
            mma16816(acc1[0][nt], ah0, b.z, b.w);
            mma16816(acc1[1][nt], ah1, b.z, b.w);
        }
    }

    __syncthreads();   // A1 reads done before H overwrites the region

    // ---- epilogue1: H = relu(D1 + b1) -> fp16 hi only ----
    const int nbase1 = nb8_1 * 8;
#pragma unroll
    for (int mt = 0; mt < 2; mt++) {
#pragma unroll
        for (int nt = 0; nt < 8; nt++) {
            const int r0 = mbase + mt * 16 + (lane >> 2);
            const int c0 = nbase1 + nt * 8 + 2 * (lane & 3);
            const float* a = acc1[mt][nt];
            float v00 = fmaxf(a[0] + b1s[c0], 0.0f);
            float v01 = fmaxf(a[1] + b1s[c0 + 1], 0.0f);
            float v10 = fmaxf(a[2] + b1s[c0], 0.0f);
            float v11 = fmaxf(a[3] + b1s[c0 + 1], 0.0f);
            *(uint32_t*)(smem + OFF_HHI + r0 * S2B + c0 * 2) =
                pack2(__float2half_rn(v00), __float2half_rn(v01));
            *(uint32_t*)(smem + OFF_HHI + (r0 + 8) * S2B + c0 * 2) =
                pack2(__float2half_rn(v10), __float2half_rn(v11));
        }
    }
    __syncthreads();

    // ---- GEMM2: D2[32m x 32n] per warp = H_hi @ (W2_hi + W2_lo)^T, 2-pass ----
    const int nb8_2 = (wid >> 1) * 4;      // n8 base (4 n-tiles per warp)
    const uint32_t a_lane2 = (uint32_t)((lane & 15) * S2B + (lane >> 4) * 16);
    const uint32_t abhi2 = smem_u + OFF_HHI + mbase * S2B + a_lane2;

    float acc2[2][4][4];
#pragma unroll
    for (int i = 0; i < 2; i++)
#pragma unroll
        for (int j = 0; j < 4; j++)
#pragma unroll
            for (int q = 0; q < 4; q++) acc2[i][j][q] = 0.0f;

#pragma unroll
    for (int ks = 0; ks < 8; ks++) {
        uint32_t ah0[4], ah1[4];
        ldsm_x4(ah0, abhi2 + ks * 32);
        ldsm_x4(ah1, abhi2 + 16 * S2B + ks * 32);
        const uint4* wp = g_w2frag + ((f * 8 + ks) * 8 + nb8_2) * 32 + lane;
#pragma unroll
        for (int nt = 0; nt < 4; nt++) {
            uint4 b = wp[nt * 32];
            mma16816(acc2[0][nt], ah0, b.x, b.y);
            mma16816(acc2[1][nt], ah1, b.x, b.y);
            mma16816(acc2[0][nt], ah0, b.z, b.w);
            mma16816(acc2[1][nt], ah1, b.z, b.w);
        }
    }

    // ---- epilogue2: out = D2 + b2 ----
    const int nbase2 = nb8_2 * 8;
#pragma unroll
    for (int mt = 0; mt < 2; mt++) {
#pragma unroll
        for (int nt = 0; nt < 4; nt++) {
            const int gm = row0 + mbase + mt * 16 + (lane >> 2);
            const int o  = nbase2 + nt * 8 + 2 * (lane & 3);
            const float* a = acc2[mt][nt];
            float2 r0, r1;
            r0.x = a[0] + b2s[o];
            r0.y = a[1] + b2s[o + 1];
            r1.x = a[2] + b2s[o];
            r1.y = a[3] + b2s[o + 1];
            *(float2*)(out + ((size_t)f * NB + gm) * NO + o) = r0;
            *(float2*)(out + ((size_t)f * NB + gm + 8) * NO + o) = r1;
        }
    }
}

extern "C" void kernel_launch(void* const* d_in, const int* in_sizes, int n_in,
                              void* d_out, int out_size) {
    const int*   inputs_raw = (const int*)d_in[0];
    const float* tables     = (const float*)d_in[1];
    const float* W1         = (const float*)d_in[2];
    const float* b1         = (const float*)d_in[3];
    const float* W2         = (const float*)d_in[4];
    const float* b2         = (const float*)d_in[5];
    float*       out        = (float*)d_out;

    cudaFuncSetAttribute(sparse_hmma_kernel,
                         cudaFuncAttributeMaxDynamicSharedMemorySize, SMEM_BYTES);

    prep_kernel<<<256, 256>>>(W1, W2, inputs_raw);

    dim3 grid(NB / TILE_B, NF);
    sparse_hmma_kernel<<<grid, 128, SMEM_BYTES>>>(inputs_raw, tables, b1, b2, out);
}

// round 15
// speedup vs baseline: 2.5540x; 1.2603x over previous
#include <cuda_runtime.h>
#include <cuda_fp16.h>
#include <cstdint>

#define NF    16
#define NB    32768
#define NE    64
#define NO    64
#define NH    128
#define NHASH 200000
#define TILE_B 64

// fp16 tile strides (bytes)
#define S1B 144     // A1: K=64 halves + 8 pad
#define S2B 272     // H : K=128 halves + 8 pad

// dynamic smem byte offsets (H aliases A1)
#define OFF_A1HI 0              // 64 x 144 = 9216
#define OFF_HHI  0              // 64 x 272 = 17408
#define SMEM_BYTES 17408

// 1-pass weight fragments (fp16 rounded once), dense uint2 per lane:
// g_w1p[((f*4 + ks)*16 + n8)*32 + lane] = {b0, b1}
//   b0 = {W[k0][n], W[k0+1][n]},  b1 = {W[k0+8][n], W[k0+9][n]}
//   n = n8*8 + (lane>>2), k0 = ks*16 + (lane&3)*2
__device__ __align__(16) uint2 g_w1p[NF * 4 * 16 * 32];   // 256 KB
__device__ __align__(16) uint2 g_w2p[NF * 8 * 8 * 32];    // 256 KB
__device__ int g_idx_is64;

__device__ __forceinline__ uint32_t smem_u32(const void* p) {
    uint32_t a;
    asm("{ .reg .u64 t; cvta.to.shared.u64 t, %1; cvt.u32.u64 %0, t; }" : "=r"(a) : "l"(p));
    return a;
}

__device__ __forceinline__ void ldsm_x4(uint32_t* r, uint32_t addr) {
    asm volatile("ldmatrix.sync.aligned.m8n8.x4.shared.b16 {%0,%1,%2,%3}, [%4];"
                 : "=r"(r[0]), "=r"(r[1]), "=r"(r[2]), "=r"(r[3]) : "r"(addr));
}

__device__ __forceinline__ void mma16816(float* d, const uint32_t* a, uint32_t b0, uint32_t b1) {
    asm volatile(
        "mma.sync.aligned.m16n8k16.row.col.f32.f16.f16.f32 "
        "{%0,%1,%2,%3}, {%4,%5,%6,%7}, {%8,%9}, {%0,%1,%2,%3};"
        : "+f"(d[0]), "+f"(d[1]), "+f"(d[2]), "+f"(d[3])
        : "r"(a[0]), "r"(a[1]), "r"(a[2]), "r"(a[3]), "r"(b0), "r"(b1));
}

__device__ __forceinline__ uint32_t pack2(__half a, __half b) {
    __half2 p = __halves2half2(a, b);
    return *reinterpret_cast<uint32_t*>(&p);
}

// ---------------- prep: idx dtype detect + weight fragment build ----------------
__global__ void prep_kernel(const float* __restrict__ W1,
                            const float* __restrict__ W2,
                            const int*   __restrict__ raw) {
    int g = blockIdx.x * blockDim.x + threadIdx.x;
    if (g == 0) {
        int any = 0;
#pragma unroll
        for (int i = 0; i < 64; i++) any |= raw[2 * i + 1];
        g_idx_is64 = (any == 0) ? 1 : 0;
    }
    if (g < NF * 4 * 16 * 32) {
        const int l  = g & 31;
        const int n8 = (g >> 5) & 15;
        const int ks = (g >> 9) & 3;
        const int f  = g >> 11;
        const int n  = n8 * 8 + (l >> 2);
        const int k0 = ks * 16 + (l & 3) * 2;
        const float* Wf = W1 + (size_t)f * NE * NH;
        uint2 r;
        r.x = pack2(__float2half_rn(Wf[(k0 + 0) * NH + n]),
                    __float2half_rn(Wf[(k0 + 1) * NH + n]));
        r.y = pack2(__float2half_rn(Wf[(k0 + 8) * NH + n]),
                    __float2half_rn(Wf[(k0 + 9) * NH + n]));
        g_w1p[g] = r;
    } else {
        g -= NF * 4 * 16 * 32;
        const int l  = g & 31;
        const int n8 = (g >> 5) & 7;
        const int ks = (g >> 8) & 7;
        const int f  = g >> 11;
        const int n  = n8 * 8 + (l >> 2);
        const int k0 = ks * 16 + (l & 3) * 2;
        const float* Wf = W2 + (size_t)f * NH * NO;
        uint2 r;
        r.x = pack2(__float2half_rn(Wf[(k0 + 0) * NO + n]),
                    __float2half_rn(Wf[(k0 + 1) * NO + n]));
        r.y = pack2(__float2half_rn(Wf[(k0 + 8) * NO + n]),
                    __float2half_rn(Wf[(k0 + 9) * NO + n]));
        g_w2p[g] = r;
    }
}

// ---------------- main kernel (128 threads, 4 warps, 64-row tile) ----------------
__global__ __launch_bounds__(128, 4) void sparse_hmma_kernel(
    const int*   __restrict__ inputs_raw,
    const float* __restrict__ tables,
    const float* __restrict__ b1,
    const float* __restrict__ b2,
    float*       __restrict__ out)
{
    extern __shared__ char smem[];
    __shared__ float b1s[NH];
    __shared__ float b2s[NO];

    const uint32_t smem_u = smem_u32(smem);
    const int tid  = threadIdx.x;
    const int wid  = tid >> 5;
    const int lane = tid & 31;
    const int f    = blockIdx.y;
    const int row0 = blockIdx.x * TILE_B;
    const int is64 = g_idx_is64;

    if (tid < NH) b1s[tid] = b1[f * NH + tid];
    if (tid < NO) b2s[tid] = b2[f * NO + tid];

    // ---- gather A1 = emb tile [m=64][k=64], fp16, 16B STS ----
    {
        const int m  = tid >> 1;
        const int hf = tid & 1;
        const int flat = (row0 + m) * NF + f;
        const int v = is64 ? inputs_raw[2 * flat] : inputs_raw[flat];
        const int hidx = (v + 1) % NHASH;
        const float4* src =
            (const float4*)(tables + ((size_t)f * NHASH + hidx) * NE + hf * 32);
#pragma unroll
        for (int i = 0; i < 4; i++) {
            float4 va = src[2 * i];
            float4 vb = src[2 * i + 1];
            const int k = hf * 32 + i * 8;
            uint4 rhi;
            rhi.x = pack2(__float2half_rn(va.x), __float2half_rn(va.y));
            rhi.y = pack2(__float2half_rn(va.z), __float2half_rn(va.w));
            rhi.z = pack2(__float2half_rn(vb.x), __float2half_rn(vb.y));
            rhi.w = pack2(__float2half_rn(vb.z), __float2half_rn(vb.w));
            *(uint4*)(smem + OFF_A1HI + m * S1B + k * 2) = rhi;
        }
    }
    __syncthreads();

    // ---- GEMM1: D1[32m x 64n] per warp = emb @ W1^T, 1-pass fp16 ----
    const int mbase = (wid & 1) * 32;
    const int nb8_1 = (wid >> 1) * 8;      // n8 base (8 n-tiles per warp)
    const uint32_t a_lane1 = (uint32_t)((lane & 15) * S1B + (lane >> 4) * 16);
    const uint32_t abhi1 = smem_u + OFF_A1HI + mbase * S1B + a_lane1;

    float acc1[2][8][4];
#pragma unroll
    for (int i = 0; i < 2; i++)
#pragma unroll
        for (int j = 0; j < 8; j++)
#pragma unroll
            for (int q = 0; q < 4; q++) acc1[i][j][q] = 0.0f;

#pragma unroll
    for (int ks = 0; ks < 4; ks++) {
        uint32_t ah0[4], ah1[4];
        ldsm_x4(ah0, abhi1 + ks * 32);
        ldsm_x4(ah1, abhi1 + 16 * S1B + ks * 32);
        const uint2* wp = g_w1p + ((f * 4 + ks) * 16 + nb8_1) * 32 + lane;
#pragma unroll
        for (int nt = 0; nt < 8; nt++) {
            uint2 b = wp[nt * 32];
            mma16816(acc1[0][nt], ah0, b.x, b.y);
            mma16816(acc1[1][nt], ah1, b.x, b.y);
        }
    }

    __syncthreads();   // A1 reads done before H overwrites the region

    // ---- epilogue1: H = relu(D1 + b1) -> fp16 ----
    const int nbase1 = nb8_1 * 8;
#pragma unroll
    for (int mt = 0; mt < 2; mt++) {
#pragma unroll
        for (int nt = 0; nt < 8; nt++) {
            const int r0 = mbase + mt * 16 + (lane >> 2);
            const int c0 = nbase1 + nt * 8 + 2 * (lane & 3);
            const float* a = acc1[mt][nt];
            float v00 = fmaxf(a[0] + b1s[c0], 0.0f);
            float v01 = fmaxf(a[1] + b1s[c0 + 1], 0.0f);
            float v10 = fmaxf(a[2] + b1s[c0], 0.0f);
            float v11 = fmaxf(a[3] + b1s[c0 + 1], 0.0f);
            *(uint32_t*)(smem + OFF_HHI + r0 * S2B + c0 * 2) =
                pack2(__float2half_rn(v00), __float2half_rn(v01));
            *(uint32_t*)(smem + OFF_HHI + (r0 + 8) * S2B + c0 * 2) =
                pack2(__float2half_rn(v10), __float2half_rn(v11));
        }
    }
    __syncthreads();

    // ---- GEMM2: D2[32m x 32n] per warp = H @ W2^T, 1-pass fp16 ----
    const int nb8_2 = (wid >> 1) * 4;      // n8 base (4 n-tiles per warp)
    const uint32_t a_lane2 = (uint32_t)((lane & 15) * S2B + (lane >> 4) * 16);
    const uint32_t abhi2 = smem_u + OFF_HHI + mbase * S2B + a_lane2;

    float acc2[2][4][4];
#pragma unroll
    for (int i = 0; i < 2; i++)
#pragma unroll
        for (int j = 0; j < 4; j++)
#pragma unroll
            for (int q = 0; q < 4; q++) acc2[i][j][q] = 0.0f;

#pragma unroll
    for (int ks = 0; ks < 8; ks++) {
        uint32_t ah0[4], ah1[4];
        ldsm_x4(ah0, abhi2 + ks * 32);
        ldsm_x4(ah1, abhi2 + 16 * S2B + ks * 32);
        const uint2* wp = g_w2p + ((f * 8 + ks) * 8 + nb8_2) * 32 + lane;
#pragma unroll
        for (int nt = 0; nt < 4; nt++) {
            uint2 b = wp[nt * 32];
            mma16816(acc2[0][nt], ah0, b.x, b.y);
            mma16816(acc2[1][nt], ah1, b.x, b.y);
        }
    }

    // ---- epilogue2: out = D2 + b2 ----
    const int nbase2 = nb8_2 * 8;
#pragma unroll
    for (int mt = 0; mt < 2; mt++) {
#pragma unroll
        for (int nt = 0; nt < 4; nt++) {
            const int gm = row0 + mbase + mt * 16 + (lane >> 2);
            const int o  = nbase2 + nt * 8 + 2 * (lane & 3);
            const float* a = acc2[mt][nt];
            float2 r0, r1;
            r0.x = a[0] + b2s[o];
            r0.y = a[1] + b2s[o + 1];
            r1.x = a[2] + b2s[o];
            r1.y = a[3] + b2s[o + 1];
            *(float2*)(out + ((size_t)f * NB + gm) * NO + o) = r0;
            *(float2*)(out + ((size_t)f * NB + gm + 8) * NO + o) = r1;
        }
    }
}

extern "C" void kernel_launch(void* const* d_in, const int* in_sizes, int n_in,
                              void* d_out, int out_size) {
    const int*   inputs_raw = (const int*)d_in[0];
    const float* tables     = (const float*)d_in[1];
    const float* W1         = (const float*)d_in[2];
    const float* b1         = (const float*)d_in[3];
    const float* W2         = (const float*)d_in[4];
    const float* b2         = (const float*)d_in[5];
    float*       out        = (float*)d_out;

    cudaFuncSetAttribute(sparse_hmma_kernel,
                         cudaFuncAttributeMaxDynamicSharedMemorySize, SMEM_BYTES);

    prep_kernel<<<256, 256>>>(W1, W2, inputs_raw);

    dim3 grid(NB / TILE_B, NF);
    sparse_hmma_kernel<<<grid, 128, SMEM_BYTES>>>(inputs_raw, tables, b1, b2, out);
}

// round 16
// speedup vs baseline: 3.1900x; 1.2490x over previous
#include <cuda_runtime.h>
#include <cuda_fp16.h>
#include <cstdint>

#define NF    16
#define NB    32768
#define NE    64
#define NO    64
#define NH    128
#define NHASH 200000
#define TILE_B 64

// fp16 tile strides (bytes)
#define S1B 144     // A1: K=64 halves + 8 pad
#define S2B 272     // H : K=128 halves + 8 pad

// dynamic smem byte offsets (H aliases A1)
#define OFF_A1HI 0              // 64 x 144 = 9216
#define OFF_HHI  0              // 64 x 272 = 17408
#define SMEM_BYTES 17408

// 1-pass weight fragments (fp16 rounded once), dense uint2 per lane:
// g_w1p[((f*4 + ks)*16 + n8)*32 + lane] = {b0, b1}
__device__ __align__(16) uint2 g_w1p[NF * 4 * 16 * 32];   // 256 KB
__device__ __align__(16) uint2 g_w2p[NF * 8 * 8 * 32];    // 256 KB
__device__ int g_idx_is64;

__device__ __forceinline__ uint32_t smem_u32(const void* p) {
    uint32_t a;
    asm("{ .reg .u64 t; cvta.to.shared.u64 t, %1; cvt.u32.u64 %0, t; }" : "=r"(a) : "l"(p));
    return a;
}

__device__ __forceinline__ void ldsm_x4(uint32_t* r, uint32_t addr) {
    asm volatile("ldmatrix.sync.aligned.m8n8.x4.shared.b16 {%0,%1,%2,%3}, [%4];"
                 : "=r"(r[0]), "=r"(r[1]), "=r"(r[2]), "=r"(r[3]) : "r"(addr));
}

__device__ __forceinline__ void mma16816(float* d, const uint32_t* a, uint32_t b0, uint32_t b1) {
    asm volatile(
        "mma.sync.aligned.m16n8k16.row.col.f32.f16.f16.f32 "
        "{%0,%1,%2,%3}, {%4,%5,%6,%7}, {%8,%9}, {%0,%1,%2,%3};"
        : "+f"(d[0]), "+f"(d[1]), "+f"(d[2]), "+f"(d[3])
        : "r"(a[0]), "r"(a[1]), "r"(a[2]), "r"(a[3]), "r"(b0), "r"(b1));
}

__device__ __forceinline__ uint32_t pack2(__half a, __half b) {
    __half2 p = __halves2half2(a, b);
    return *reinterpret_cast<uint32_t*>(&p);
}

// ---------------- prep: idx dtype detect + weight fragment build ----------------
__global__ void prep_kernel(const float* __restrict__ W1,
                            const float* __restrict__ W2,
                            const int*   __restrict__ raw) {
    int g = blockIdx.x * blockDim.x + threadIdx.x;
    if (g == 0) {
        int any = 0;
#pragma unroll
        for (int i = 0; i < 64; i++) any |= raw[2 * i + 1];
        g_idx_is64 = (any == 0) ? 1 : 0;
    }
    if (g < NF * 4 * 16 * 32) {
        const int l  = g & 31;
        const int n8 = (g >> 5) & 15;
        const int ks = (g >> 9) & 3;
        const int f  = g >> 11;
        const int n  = n8 * 8 + (l >> 2);
        const int k0 = ks * 16 + (l & 3) * 2;
        const float* Wf = W1 + (size_t)f * NE * NH;
        uint2 r;
        r.x = pack2(__float2half_rn(Wf[(k0 + 0) * NH + n]),
                    __float2half_rn(Wf[(k0 + 1) * NH + n]));
        r.y = pack2(__float2half_rn(Wf[(k0 + 8) * NH + n]),
                    __float2half_rn(Wf[(k0 + 9) * NH + n]));
        g_w1p[g] = r;
    } else {
        g -= NF * 4 * 16 * 32;
        const int l  = g & 31;
        const int n8 = (g >> 5) & 7;
        const int ks = (g >> 8) & 7;
        const int f  = g >> 11;
        const int n  = n8 * 8 + (l >> 2);
        const int k0 = ks * 16 + (l & 3) * 2;
        const float* Wf = W2 + (size_t)f * NH * NO;
        uint2 r;
        r.x = pack2(__float2half_rn(Wf[(k0 + 0) * NO + n]),
                    __float2half_rn(Wf[(k0 + 1) * NO + n]));
        r.y = pack2(__float2half_rn(Wf[(k0 + 8) * NO + n]),
                    __float2half_rn(Wf[(k0 + 9) * NO + n]));
        g_w2p[g] = r;
    }
}

// ---------------- main kernel (128 threads, 4 warps, 64-row tile) ----------------
__global__ __launch_bounds__(128, 4) void sparse_hmma_kernel(
    const int*   __restrict__ inputs_raw,
    const float* __restrict__ tables,
    const float* __restrict__ b1,
    const float* __restrict__ b2,
    float*       __restrict__ out)
{
    extern __shared__ char smem[];
    __shared__ float b1s[NH];
    __shared__ float b2s[NO];

    const uint32_t smem_u = smem_u32(smem);
    const int tid  = threadIdx.x;
    const int wid  = tid >> 5;
    const int lane = tid & 31;
    const int f    = blockIdx.y;
    const int row0 = blockIdx.x * TILE_B;
    const int is64 = g_idx_is64;

    if (tid < NH) b1s[tid] = b1[f * NH + tid];
    if (tid < NO) b2s[tid] = b2[f * NO + tid];

    // ---- gather A1 = emb tile [m=64][k=64], fp16, line-coalesced ----
    // 8 lanes per row: lanes 8j..8j+7 read consecutive 16B chunks of the
    // same 128B line -> 1 L1 wavefront per line (optimal).
    {
        const int r16 = tid >> 3;      // row within round (0..15)
        const int c8  = tid & 7;       // 16B-chunk index within a 128B line
#pragma unroll
        for (int round = 0; round < 4; round++) {
            const int m = round * 16 + r16;
            const int flat = (row0 + m) * NF + f;
            const int v = is64 ? inputs_raw[2 * flat] : inputs_raw[flat];
            const int hidx = (v + 1) % NHASH;
            const float4* src =
                (const float4*)(tables + ((size_t)f * NHASH + hidx) * NE) + c8;
            float4 va = src[0];   // bytes [c8*16, +16) of line 0
            float4 vb = src[8];   // bytes [c8*16, +16) of line 1
            uint2 p0, p1;
            p0.x = pack2(__float2half_rn(va.x), __float2half_rn(va.y));
            p0.y = pack2(__float2half_rn(va.z), __float2half_rn(va.w));
            p1.x = pack2(__float2half_rn(vb.x), __float2half_rn(vb.y));
            p1.y = pack2(__float2half_rn(vb.z), __float2half_rn(vb.w));
            *(uint2*)(smem + OFF_A1HI + m * S1B + c8 * 8)      = p0;
            *(uint2*)(smem + OFF_A1HI + m * S1B + 64 + c8 * 8) = p1;
        }
    }
    __syncthreads();

    // ---- GEMM1: D1[32m x 64n] per warp = emb @ W1^T, 1-pass fp16 ----
    const int mbase = (wid & 1) * 32;
    const int nb8_1 = (wid >> 1) * 8;      // n8 base (8 n-tiles per warp)
    const uint32_t a_lane1 = (uint32_t)((lane & 15) * S1B + (lane >> 4) * 16);
    const uint32_t abhi1 = smem_u + OFF_A1HI + mbase * S1B + a_lane1;

    float acc1[2][8][4];
#pragma unroll
    for (int i = 0; i < 2; i++)
#pragma unroll
        for (int j = 0; j < 8; j++)
#pragma unroll
            for (int q = 0; q < 4; q++) acc1[i][j][q] = 0.0f;

#pragma unroll
    for (int ks = 0; ks < 4; ks++) {
        uint32_t ah0[4], ah1[4];
        ldsm_x4(ah0, abhi1 + ks * 32);
        ldsm_x4(ah1, abhi1 + 16 * S1B + ks * 32);
        const uint2* wp = g_w1p + ((f * 4 + ks) * 16 + nb8_1) * 32 + lane;
#pragma unroll
        for (int nt = 0; nt < 8; nt++) {
            uint2 b = wp[nt * 32];
            mma16816(acc1[0][nt], ah0, b.x, b.y);
            mma16816(acc1[1][nt], ah1, b.x, b.y);
        }
    }

    __syncthreads();   // A1 reads done before H overwrites the region

    // ---- epilogue1: H = relu(D1 + b1) -> fp16 ----
    const int nbase1 = nb8_1 * 8;
#pragma unroll
    for (int mt = 0; mt < 2; mt++) {
#pragma unroll
        for (int nt = 0; nt < 8; nt++) {
            const int r0 = mbase + mt * 16 + (lane >> 2);
            const int c0 = nbase1 + nt * 8 + 2 * (lane & 3);
            const float* a = acc1[mt][nt];
            float v00 = fmaxf(a[0] + b1s[c0], 0.0f);
            float v01 = fmaxf(a[1] + b1s[c0 + 1], 0.0f);
            float v10 = fmaxf(a[2] + b1s[c0], 0.0f);
            float v11 = fmaxf(a[3] + b1s[c0 + 1], 0.0f);
            *(uint32_t*)(smem + OFF_HHI + r0 * S2B + c0 * 2) =
                pack2(__float2half_rn(v00), __float2half_rn(v01));
            *(uint32_t*)(smem + OFF_HHI + (r0 + 8) * S2B + c0 * 2) =
                pack2(__float2half_rn(v10), __float2half_rn(v11));
        }
    }
    __syncthreads();

    // ---- GEMM2: D2[32m x 32n] per warp = H @ W2^T, 1-pass fp16 ----
    const int nb8_2 = (wid >> 1) * 4;      // n8 base (4 n-tiles per warp)
    const uint32_t a_lane2 = (uint32_t)((lane & 15) * S2B + (lane >> 4) * 16);
    const uint32_t abhi2 = smem_u + OFF_HHI + mbase * S2B + a_lane2;

    float acc2[2][4][4];
#pragma unroll
    for (int i = 0; i < 2; i++)
#pragma unroll
        for (int j = 0; j < 4; j++)
#pragma unroll
            for (int q = 0; q < 4; q++) acc2[i][j][q] = 0.0f;

#pragma unroll
    for (int ks = 0; ks < 8; ks++) {
        uint32_t ah0[4], ah1[4];
        ldsm_x4(ah0, abhi2 + ks * 32);
        ldsm_x4(ah1, abhi2 + 16 * S2B + ks * 32);
        const uint2* wp = g_w2p + ((f * 8 + ks) * 8 + nb8_2) * 32 + lane;
#pragma unroll
        for (int nt = 0; nt < 4; nt++) {
            uint2 b = wp[nt * 32];
            mma16816(acc2[0][nt], ah0, b.x, b.y);
            mma16816(acc2[1][nt], ah1, b.x, b.y);
        }
    }

    // ---- epilogue2: out = D2 + b2 ----
    const int nbase2 = nb8_2 * 8;
#pragma unroll
    for (int mt = 0; mt < 2; mt++) {
#pragma unroll
        for (int nt = 0; nt < 4; nt++) {
            const int gm = row0 + mbase + mt * 16 + (lane >> 2);
            const int o  = nbase2 + nt * 8 + 2 * (lane & 3);
            const float* a = acc2[mt][nt];
            float2 r0, r1;
            r0.x = a[0] + b2s[o];
            r0.y = a[1] + b2s[o + 1];
            r1.x = a[2] + b2s[o];
            r1.y = a[3] + b2s[o + 1];
            *(float2*)(out + ((size_t)f * NB + gm) * NO + o) = r0;
            *(float2*)(out + ((size_t)f * NB + gm + 8) * NO + o) = r1;
        }
    }
}

extern "C" void kernel_launch(void* const* d_in, const int* in_sizes, int n_in,
                              void* d_out, int out_size) {
    const int*   inputs_raw = (const int*)d_in[0];
    const float* tables     = (const float*)d_in[1];
    const float* W1         = (const float*)d_in[2];
    const float* b1         = (const float*)d_in[3];
    const float* W2         = (const float*)d_in[4];
    const float* b2         = (const float*)d_in[5];
    float*       out        = (float*)d_out;

    cudaFuncSetAttribute(sparse_hmma_kernel,
                         cudaFuncAttributeMaxDynamicSharedMemorySize, SMEM_BYTES);

    prep_kernel<<<256, 256>>>(W1, W2, inputs_raw);

    dim3 grid(NB / TILE_B, NF);
    sparse_hmma_kernel<<<grid, 128, SMEM_BYTES>>>(inputs_raw, tables, b1, b2, out);
}